// round 2
// baseline (speedup 1.0000x reference)
#include <cuda_runtime.h>
#include <cuda_bf16.h>

#define M_NODES 10000
#define K_IN    512
#define N_HID   512
#define N_EDGES 160000

// Scratch for x_fts = x @ fc_w^T  (20.48 MB, fits in L2 for the SPMM phase)
__device__ float g_xfts[M_NODES * N_HID];

// ---------------------------------------------------------------------------
// GEMM: x_fts[m][n] = sum_k X[m][k] * W[n][k]   (both K-major, "NT" layout)
// 64x64 tile, BK=32, 256 threads, 4x4 micro-tile per thread.
// ---------------------------------------------------------------------------
__global__ __launch_bounds__(256) void gemm_nt_kernel(
    const float* __restrict__ X,   // [M_NODES, K_IN]
    const float* __restrict__ W)   // [N_HID,  K_IN]
{
    __shared__ float As[32][65];   // [k][m], pad 65 -> conflict-free strided writes
    __shared__ float Bs[32][65];   // [k][n]

    const int tid = threadIdx.x;
    const int tx  = tid & 15;      // 0..15 -> n micro
    const int ty  = tid >> 4;      // 0..15 -> m micro
    const int m0  = blockIdx.y * 64;
    const int n0  = blockIdx.x * 64;

    float acc[4][4];
#pragma unroll
    for (int i = 0; i < 4; i++)
#pragma unroll
        for (int j = 0; j < 4; j++) acc[i][j] = 0.f;

    const int lr = tid >> 5;       // 0..7  row group
    const int lc = tid & 31;       // 0..31 k within tile

    for (int k0 = 0; k0 < K_IN; k0 += 32) {
#pragma unroll
        for (int p = 0; p < 8; p++) {
            int r  = lr + p * 8;               // 0..63
            int gm = m0 + r;
            As[lc][r] = (gm < M_NODES) ? X[(size_t)gm * K_IN + k0 + lc] : 0.f;
            Bs[lc][r] = W[(size_t)(n0 + r) * K_IN + k0 + lc];   // n0+r < 512 always
        }
        __syncthreads();

#pragma unroll
        for (int kk = 0; kk < 32; kk++) {
            float a[4], b[4];
#pragma unroll
            for (int i = 0; i < 4; i++) a[i] = As[kk][ty * 4 + i];
#pragma unroll
            for (int j = 0; j < 4; j++) b[j] = Bs[kk][tx * 4 + j];
#pragma unroll
            for (int i = 0; i < 4; i++)
#pragma unroll
                for (int j = 0; j < 4; j++) acc[i][j] += a[i] * b[j];
        }
        __syncthreads();
    }

#pragma unroll
    for (int i = 0; i < 4; i++) {
        int gm = m0 + ty * 4 + i;
        if (gm >= M_NODES) continue;
        float* dst = &g_xfts[(size_t)gm * N_HID + n0 + tx * 4];
        float4 v = make_float4(acc[i][0], acc[i][1], acc[i][2], acc[i][3]);
        *reinterpret_cast<float4*>(dst) = v;
    }
}

// ---------------------------------------------------------------------------
// SPMM + bias + PReLU.  adj_row is sorted -> one CTA per output row,
// binary-search edge range, accumulate in registers, no atomics.
// 128 threads x float4 = 512 channels.
// NOTE: adj_row / adj_col arrive as int32 (JAX default x64-disabled downcast).
// ---------------------------------------------------------------------------
__global__ __launch_bounds__(128) void spmm_bias_prelu_kernel(
    const float* __restrict__ adj_vals,
    const int* __restrict__ adj_row,
    const int* __restrict__ adj_col,
    const float* __restrict__ bias,
    const float* __restrict__ prelu_a,
    float* __restrict__ out)
{
    const int r   = blockIdx.x;
    const int c   = threadIdx.x * 4;

    // lower_bound(adj_row, r) and lower_bound(adj_row, r+1)
    int lo = 0, hi = N_EDGES;
    while (lo < hi) {
        int mid = (lo + hi) >> 1;
        if (adj_row[mid] < r) lo = mid + 1; else hi = mid;
    }
    const int start = lo;
    hi = N_EDGES;
    while (lo < hi) {
        int mid = (lo + hi) >> 1;
        if (adj_row[mid] < r + 1) lo = mid + 1; else hi = mid;
    }
    const int end = lo;

    float4 acc = make_float4(0.f, 0.f, 0.f, 0.f);
    for (int e = start; e < end; e++) {
        const float v = __ldg(&adj_vals[e]);
        const int col = __ldg(&adj_col[e]);
        const float4 f = *reinterpret_cast<const float4*>(
            &g_xfts[(size_t)col * N_HID + c]);
        acc.x += v * f.x;
        acc.y += v * f.y;
        acc.z += v * f.z;
        acc.w += v * f.w;
    }

    const float4 b4 = *reinterpret_cast<const float4*>(&bias[c]);
    const float a = *prelu_a;
    acc.x += b4.x; acc.y += b4.y; acc.z += b4.z; acc.w += b4.w;
    acc.x = (acc.x >= 0.f) ? acc.x : a * acc.x;
    acc.y = (acc.y >= 0.f) ? acc.y : a * acc.y;
    acc.z = (acc.z >= 0.f) ? acc.z : a * acc.z;
    acc.w = (acc.w >= 0.f) ? acc.w : a * acc.w;

    *reinterpret_cast<float4*>(&out[(size_t)r * N_HID + c]) = acc;
}

extern "C" void kernel_launch(void* const* d_in, const int* in_sizes, int n_in,
                              void* d_out, int out_size)
{
    const float* x        = (const float*)d_in[0];       // [10000, 512]
    const float* fc_w     = (const float*)d_in[1];       // [512, 512]
    const float* bias     = (const float*)d_in[2];       // [512]
    const float* prelu_a  = (const float*)d_in[3];       // [1]
    const float* adj_vals = (const float*)d_in[4];       // [160000]
    const int*   adj_row  = (const int*)d_in[5];         // [160000] sorted, int32
    const int*   adj_col  = (const int*)d_in[6];         // [160000] int32
    float*       out      = (float*)d_out;               // [10000, 512]

    dim3 ggrid(N_HID / 64, (M_NODES + 63) / 64);   // 8 x 157
    gemm_nt_kernel<<<ggrid, 256>>>(x, fc_w);

    spmm_bias_prelu_kernel<<<M_NODES, 128>>>(adj_vals, adj_row, adj_col,
                                             bias, prelu_a, out);
}

// round 3
// speedup vs baseline: 1.6714x; 1.6714x over previous
#include <cuda_runtime.h>
#include <cuda_bf16.h>
#include <cstdint>

#define M_NODES 10000
#define K_IN    512
#define N_HID   512
#define N_EDGES 160000

// Scratch (no allocations allowed): fp32 result of fc, split operands, rowptr.
__device__ float         g_xfts[M_NODES * N_HID];
__device__ __nv_bfloat16 g_xhi[M_NODES * K_IN];
__device__ __nv_bfloat16 g_xlo[M_NODES * K_IN];
__device__ __nv_bfloat16 g_whi[N_HID * K_IN];
__device__ __nv_bfloat16 g_wlo[N_HID * K_IN];
__device__ int           g_rowptr[M_NODES + 1];

// ---------------------------------------------------------------------------
// Split fp32 -> bf16 hi + bf16 lo   (a = hi + lo, |err| ~ 2^-18 |a|)
// ---------------------------------------------------------------------------
__global__ __launch_bounds__(256) void split_x_kernel(const float* __restrict__ src)
{
    int i = blockIdx.x * blockDim.x + threadIdx.x;          // float4 index
    if (i * 4 >= M_NODES * K_IN) return;
    float4 v = reinterpret_cast<const float4*>(src)[i];
    __nv_bfloat16 hx = __float2bfloat16_rn(v.x);
    __nv_bfloat16 hy = __float2bfloat16_rn(v.y);
    __nv_bfloat16 hz = __float2bfloat16_rn(v.z);
    __nv_bfloat16 hw = __float2bfloat16_rn(v.w);
    __nv_bfloat16 lx = __float2bfloat16_rn(v.x - __bfloat162float(hx));
    __nv_bfloat16 ly = __float2bfloat16_rn(v.y - __bfloat162float(hy));
    __nv_bfloat16 lz = __float2bfloat16_rn(v.z - __bfloat162float(hz));
    __nv_bfloat16 lw = __float2bfloat16_rn(v.w - __bfloat162float(hw));
    reinterpret_cast<__nv_bfloat162*>(g_xhi)[2 * i]     = __nv_bfloat162(hx, hy);
    reinterpret_cast<__nv_bfloat162*>(g_xhi)[2 * i + 1] = __nv_bfloat162(hz, hw);
    reinterpret_cast<__nv_bfloat162*>(g_xlo)[2 * i]     = __nv_bfloat162(lx, ly);
    reinterpret_cast<__nv_bfloat162*>(g_xlo)[2 * i + 1] = __nv_bfloat162(lz, lw);
}

__global__ __launch_bounds__(256) void split_w_kernel(const float* __restrict__ src)
{
    int i = blockIdx.x * blockDim.x + threadIdx.x;
    if (i * 4 >= N_HID * K_IN) return;
    float4 v = reinterpret_cast<const float4*>(src)[i];
    __nv_bfloat16 hx = __float2bfloat16_rn(v.x);
    __nv_bfloat16 hy = __float2bfloat16_rn(v.y);
    __nv_bfloat16 hz = __float2bfloat16_rn(v.z);
    __nv_bfloat16 hw = __float2bfloat16_rn(v.w);
    __nv_bfloat16 lx = __float2bfloat16_rn(v.x - __bfloat162float(hx));
    __nv_bfloat16 ly = __float2bfloat16_rn(v.y - __bfloat162float(hy));
    __nv_bfloat16 lz = __float2bfloat16_rn(v.z - __bfloat162float(hz));
    __nv_bfloat16 lw = __float2bfloat16_rn(v.w - __bfloat162float(hw));
    reinterpret_cast<__nv_bfloat162*>(g_whi)[2 * i]     = __nv_bfloat162(hx, hy);
    reinterpret_cast<__nv_bfloat162*>(g_whi)[2 * i + 1] = __nv_bfloat162(hz, hw);
    reinterpret_cast<__nv_bfloat162*>(g_wlo)[2 * i]     = __nv_bfloat162(lx, ly);
    reinterpret_cast<__nv_bfloat162*>(g_wlo)[2 * i + 1] = __nv_bfloat162(lz, lw);
}

// ---------------------------------------------------------------------------
// rowptr[i] = lower_bound(adj_row, i)
// ---------------------------------------------------------------------------
__global__ __launch_bounds__(256) void rowptr_kernel(const int* __restrict__ adj_row)
{
    int r = blockIdx.x * blockDim.x + threadIdx.x;
    if (r > M_NODES) return;
    int lo = 0, hi = N_EDGES;
    while (lo < hi) {
        int mid = (lo + hi) >> 1;
        if (adj_row[mid] < r) lo = mid + 1; else hi = mid;
    }
    g_rowptr[r] = lo;
}

// ---------------------------------------------------------------------------
// Tensor-core GEMM: x_fts = X @ W^T with bf16 split (hi*hi + hi*lo + lo*hi).
// CTA 128x128, BK=32, 4 warps (2x2), warp tile 64x64, cp.async double buffer.
// ---------------------------------------------------------------------------
#define BM 128
#define BN 128
#define BK 32
#define KSTRIDE 40                 // bf16 per smem row (32 + 8 pad)
#define ASPLIT  (128 * KSTRIDE)    // 5120 bf16 per split-tile
#define ABUF    (2 * ASPLIT)       // hi+lo
#define B_BASE  (2 * ABUF)         // B region starts after A double buffer
#define SMEM_BF16_TOTAL (4 * ABUF) // 40960 bf16 = 81920 bytes

__device__ __forceinline__ void cp_async16(uint32_t dst, const void* src, bool pred)
{
    int sz = pred ? 16 : 0;
    asm volatile("cp.async.cg.shared.global [%0], [%1], 16, %2;\n"
                 :: "r"(dst), "l"(src), "r"(sz));
}
__device__ __forceinline__ void cp_commit() { asm volatile("cp.async.commit_group;\n"); }
__device__ __forceinline__ void cp_wait0()  { asm volatile("cp.async.wait_group 0;\n"); }

__device__ __forceinline__ void mma_bf16(float c[4], uint32_t a0, uint32_t a1,
                                         uint32_t a2, uint32_t a3,
                                         uint32_t b0, uint32_t b1)
{
    asm volatile(
        "mma.sync.aligned.m16n8k16.row.col.f32.bf16.bf16.f32 "
        "{%0,%1,%2,%3}, {%4,%5,%6,%7}, {%8,%9}, {%0,%1,%2,%3};\n"
        : "+f"(c[0]), "+f"(c[1]), "+f"(c[2]), "+f"(c[3])
        : "r"(a0), "r"(a1), "r"(a2), "r"(a3), "r"(b0), "r"(b1));
}

__global__ __launch_bounds__(128) void gemm_tc_kernel()
{
    extern __shared__ __nv_bfloat16 smem[];
    const int tid  = threadIdx.x;
    const int lane = tid & 31;
    const int wid  = tid >> 5;            // 0..3
    const int wm   = (wid & 1) * 64;
    const int wn   = (wid >> 1) * 64;
    const int m0   = blockIdx.y * BM;
    const int n0   = blockIdx.x * BN;
    const int grp  = lane >> 2;           // 0..7
    const int tig  = lane & 3;            // 0..3

    const uint32_t smem_u32 = (uint32_t)__cvta_generic_to_shared(smem);

    float acc[4][8][4];
#pragma unroll
    for (int mi = 0; mi < 4; mi++)
#pragma unroll
        for (int ni = 0; ni < 8; ni++)
#pragma unroll
            for (int q = 0; q < 4; q++) acc[mi][ni][q] = 0.f;

    // --- tile loader: thread t loads row t (4 chunks x 2 splits, A and B) ---
    const int row  = tid;                 // 0..127
    const int gmA  = m0 + row;
    const bool pA  = (gmA < M_NODES);
    const int gnB  = n0 + row;            // always < 512

    auto load_tile = [&](int buf, int k0) {
#pragma unroll
        for (int c = 0; c < 4; c++) {
            uint32_t dA = smem_u32 + (uint32_t)((buf * ABUF + row * KSTRIDE + c * 8) * 2);
            cp_async16(dA,            &g_xhi[(size_t)gmA * K_IN + k0 + c * 8], pA);
            cp_async16(dA + ASPLIT*2, &g_xlo[(size_t)gmA * K_IN + k0 + c * 8], pA);
            uint32_t dB = smem_u32 + (uint32_t)((B_BASE + buf * ABUF + row * KSTRIDE + c * 8) * 2);
            cp_async16(dB,            &g_whi[(size_t)gnB * K_IN + k0 + c * 8], true);
            cp_async16(dB + ASPLIT*2, &g_wlo[(size_t)gnB * K_IN + k0 + c * 8], true);
        }
        cp_commit();
    };

    load_tile(0, 0);

    const int NT = K_IN / BK;             // 16
    for (int t = 0; t < NT; t++) {
        cp_wait0();
        __syncthreads();
        if (t + 1 < NT) load_tile((t + 1) & 1, (t + 1) * BK);

        const int buf = t & 1;
        const __nv_bfloat16* sA = smem + buf * ABUF;
        const __nv_bfloat16* sB = smem + B_BASE + buf * ABUF;

#pragma unroll
        for (int ks = 0; ks < 2; ks++) {
            const int col = ks * 16 + tig * 2;
            uint32_t ahi[4][4], alo[4][4];
#pragma unroll
            for (int mi = 0; mi < 4; mi++) {
                int r0 = wm + mi * 16 + grp;
                const __nv_bfloat16* ph = sA + r0 * KSTRIDE;
                ahi[mi][0] = *(const uint32_t*)(ph + col);
                ahi[mi][1] = *(const uint32_t*)(ph + 8 * KSTRIDE + col);
                ahi[mi][2] = *(const uint32_t*)(ph + col + 8);
                ahi[mi][3] = *(const uint32_t*)(ph + 8 * KSTRIDE + col + 8);
                const __nv_bfloat16* pl = ph + ASPLIT;
                alo[mi][0] = *(const uint32_t*)(pl + col);
                alo[mi][1] = *(const uint32_t*)(pl + 8 * KSTRIDE + col);
                alo[mi][2] = *(const uint32_t*)(pl + col + 8);
                alo[mi][3] = *(const uint32_t*)(pl + 8 * KSTRIDE + col + 8);
            }
#pragma unroll
            for (int nh = 0; nh < 2; nh++) {
                uint32_t bhi[4][2], blo[4][2];
#pragma unroll
                for (int nj = 0; nj < 4; nj++) {
                    int rn = wn + (nh * 4 + nj) * 8 + grp;
                    const __nv_bfloat16* ph = sB + rn * KSTRIDE;
                    bhi[nj][0] = *(const uint32_t*)(ph + col);
                    bhi[nj][1] = *(const uint32_t*)(ph + col + 8);
                    const __nv_bfloat16* pl = ph + ASPLIT;
                    blo[nj][0] = *(const uint32_t*)(pl + col);
                    blo[nj][1] = *(const uint32_t*)(pl + col + 8);
                }
#pragma unroll
                for (int mi = 0; mi < 4; mi++)
#pragma unroll
                    for (int nj = 0; nj < 4; nj++) {
                        float* c = acc[mi][nh * 4 + nj];
                        mma_bf16(c, ahi[mi][0], ahi[mi][1], ahi[mi][2], ahi[mi][3],
                                 bhi[nj][0], bhi[nj][1]);
                        mma_bf16(c, ahi[mi][0], ahi[mi][1], ahi[mi][2], ahi[mi][3],
                                 blo[nj][0], blo[nj][1]);
                        mma_bf16(c, alo[mi][0], alo[mi][1], alo[mi][2], alo[mi][3],
                                 bhi[nj][0], bhi[nj][1]);
                    }
            }
        }
        __syncthreads();
    }

    // --- epilogue: acc -> g_xfts ---
#pragma unroll
    for (int mi = 0; mi < 4; mi++) {
        int gm = m0 + wm + mi * 16 + grp;
#pragma unroll
        for (int ni = 0; ni < 8; ni++) {
            int gn = n0 + wn + ni * 8 + tig * 2;
            if (gm < M_NODES)
                *(float2*)&g_xfts[(size_t)gm * N_HID + gn] =
                    make_float2(acc[mi][ni][0], acc[mi][ni][1]);
            if (gm + 8 < M_NODES)
                *(float2*)&g_xfts[(size_t)(gm + 8) * N_HID + gn] =
                    make_float2(acc[mi][ni][2], acc[mi][ni][3]);
        }
    }
}

// ---------------------------------------------------------------------------
// SPMM + bias + PReLU. One CTA per row via precomputed rowptr; 2-deep MLP.
// ---------------------------------------------------------------------------
__global__ __launch_bounds__(128) void spmm_bias_prelu_kernel(
    const float* __restrict__ adj_vals,
    const int* __restrict__ adj_col,
    const float* __restrict__ bias,
    const float* __restrict__ prelu_a,
    float* __restrict__ out)
{
    const int r = blockIdx.x;
    const int c = threadIdx.x * 4;
    const int start = g_rowptr[r];
    const int end   = g_rowptr[r + 1];

    float4 acc0 = make_float4(0.f, 0.f, 0.f, 0.f);
    float4 acc1 = make_float4(0.f, 0.f, 0.f, 0.f);

    int e = start;
    for (; e + 1 < end; e += 2) {
        const float v0 = __ldg(&adj_vals[e]);
        const int   c0 = __ldg(&adj_col[e]);
        const float v1 = __ldg(&adj_vals[e + 1]);
        const int   c1 = __ldg(&adj_col[e + 1]);
        const float4 f0 = *reinterpret_cast<const float4*>(&g_xfts[(size_t)c0 * N_HID + c]);
        const float4 f1 = *reinterpret_cast<const float4*>(&g_xfts[(size_t)c1 * N_HID + c]);
        acc0.x += v0 * f0.x; acc0.y += v0 * f0.y; acc0.z += v0 * f0.z; acc0.w += v0 * f0.w;
        acc1.x += v1 * f1.x; acc1.y += v1 * f1.y; acc1.z += v1 * f1.z; acc1.w += v1 * f1.w;
    }
    if (e < end) {
        const float v0 = __ldg(&adj_vals[e]);
        const int   c0 = __ldg(&adj_col[e]);
        const float4 f0 = *reinterpret_cast<const float4*>(&g_xfts[(size_t)c0 * N_HID + c]);
        acc0.x += v0 * f0.x; acc0.y += v0 * f0.y; acc0.z += v0 * f0.z; acc0.w += v0 * f0.w;
    }

    const float4 b4 = *reinterpret_cast<const float4*>(&bias[c]);
    const float a = *prelu_a;
    float4 o;
    o.x = acc0.x + acc1.x + b4.x;
    o.y = acc0.y + acc1.y + b4.y;
    o.z = acc0.z + acc1.z + b4.z;
    o.w = acc0.w + acc1.w + b4.w;
    o.x = (o.x >= 0.f) ? o.x : a * o.x;
    o.y = (o.y >= 0.f) ? o.y : a * o.y;
    o.z = (o.z >= 0.f) ? o.z : a * o.z;
    o.w = (o.w >= 0.f) ? o.w : a * o.w;
    *reinterpret_cast<float4*>(&out[(size_t)r * N_HID + c]) = o;
}

extern "C" void kernel_launch(void* const* d_in, const int* in_sizes, int n_in,
                              void* d_out, int out_size)
{
    const float* x        = (const float*)d_in[0];
    const float* fc_w     = (const float*)d_in[1];
    const float* bias     = (const float*)d_in[2];
    const float* prelu_a  = (const float*)d_in[3];
    const float* adj_vals = (const float*)d_in[4];
    const int*   adj_row  = (const int*)d_in[5];
    const int*   adj_col  = (const int*)d_in[6];
    float*       out      = (float*)d_out;

    cudaFuncSetAttribute(gemm_tc_kernel,
                         cudaFuncAttributeMaxDynamicSharedMemorySize,
                         SMEM_BF16_TOTAL * 2);

    split_x_kernel<<<(M_NODES * K_IN / 4 + 255) / 256, 256>>>(x);
    split_w_kernel<<<(N_HID * K_IN / 4 + 255) / 256, 256>>>(fc_w);
    rowptr_kernel<<<(M_NODES + 1 + 255) / 256, 256>>>(adj_row);

    dim3 ggrid(N_HID / BN, (M_NODES + BM - 1) / BM);   // 4 x 79
    gemm_tc_kernel<<<ggrid, 128, SMEM_BF16_TOTAL * 2>>>();

    spmm_bias_prelu_kernel<<<M_NODES, 128>>>(adj_vals, adj_col, bias, prelu_a, out);
}

// round 5
// speedup vs baseline: 1.7225x; 1.0306x over previous
#include <cuda_runtime.h>
#include <cuda_bf16.h>
#include <cstdint>

#define M_NODES 10000
#define K_IN    512
#define N_HID   512
#define N_EDGES 160000

// Scratch (no allocations allowed)
__device__ float         g_xfts[M_NODES * N_HID];
__device__ __nv_bfloat16 g_xhi[M_NODES * K_IN];
__device__ __nv_bfloat16 g_xlo[M_NODES * K_IN];
__device__ __nv_bfloat16 g_whi[N_HID * K_IN];
__device__ __nv_bfloat16 g_wlo[N_HID * K_IN];
__device__ int           g_rowptr[M_NODES + 1];

// ---------------------------------------------------------------------------
// Fused prep: split X, split W (fp32 -> bf16 hi+lo), build rowptr.
// Block ranges:  [0, 5000)  X float4s (1,280,000)
//                [5000, 5256) W float4s (65,536)
//                [5256, 5296) rowptr (10,001)
// ---------------------------------------------------------------------------
#define XBLK 5000
#define WBLK 256
#define RBLK 40

__global__ __launch_bounds__(256) void prep_kernel(
    const float* __restrict__ x,
    const float* __restrict__ fc_w,
    const int* __restrict__ adj_row)
{
    const int b = blockIdx.x;
    if (b < XBLK) {
        int i = b * 256 + threadIdx.x;
        if (i * 4 >= M_NODES * K_IN) return;
        float4 v = reinterpret_cast<const float4*>(x)[i];
        __nv_bfloat16 hx = __float2bfloat16_rn(v.x);
        __nv_bfloat16 hy = __float2bfloat16_rn(v.y);
        __nv_bfloat16 hz = __float2bfloat16_rn(v.z);
        __nv_bfloat16 hw = __float2bfloat16_rn(v.w);
        __nv_bfloat16 lx = __float2bfloat16_rn(v.x - __bfloat162float(hx));
        __nv_bfloat16 ly = __float2bfloat16_rn(v.y - __bfloat162float(hy));
        __nv_bfloat16 lz = __float2bfloat16_rn(v.z - __bfloat162float(hz));
        __nv_bfloat16 lw = __float2bfloat16_rn(v.w - __bfloat162float(hw));
        reinterpret_cast<__nv_bfloat162*>(g_xhi)[2 * i]     = __nv_bfloat162(hx, hy);
        reinterpret_cast<__nv_bfloat162*>(g_xhi)[2 * i + 1] = __nv_bfloat162(hz, hw);
        reinterpret_cast<__nv_bfloat162*>(g_xlo)[2 * i]     = __nv_bfloat162(lx, ly);
        reinterpret_cast<__nv_bfloat162*>(g_xlo)[2 * i + 1] = __nv_bfloat162(lz, lw);
    } else if (b < XBLK + WBLK) {
        int i = (b - XBLK) * 256 + threadIdx.x;
        if (i * 4 >= N_HID * K_IN) return;
        float4 v = reinterpret_cast<const float4*>(fc_w)[i];
        __nv_bfloat16 hx = __float2bfloat16_rn(v.x);
        __nv_bfloat16 hy = __float2bfloat16_rn(v.y);
        __nv_bfloat16 hz = __float2bfloat16_rn(v.z);
        __nv_bfloat16 hw = __float2bfloat16_rn(v.w);
        __nv_bfloat16 lx = __float2bfloat16_rn(v.x - __bfloat162float(hx));
        __nv_bfloat16 ly = __float2bfloat16_rn(v.y - __bfloat162float(hy));
        __nv_bfloat16 lz = __float2bfloat16_rn(v.z - __bfloat162float(hz));
        __nv_bfloat16 lw = __float2bfloat16_rn(v.w - __bfloat162float(hw));
        reinterpret_cast<__nv_bfloat162*>(g_whi)[2 * i]     = __nv_bfloat162(hx, hy);
        reinterpret_cast<__nv_bfloat162*>(g_whi)[2 * i + 1] = __nv_bfloat162(hz, hw);
        reinterpret_cast<__nv_bfloat162*>(g_wlo)[2 * i]     = __nv_bfloat162(lx, ly);
        reinterpret_cast<__nv_bfloat162*>(g_wlo)[2 * i + 1] = __nv_bfloat162(lz, lw);
    } else {
        int r = (b - XBLK - WBLK) * 256 + threadIdx.x;
        if (r > M_NODES) return;
        int lo = 0, hi = N_EDGES;
        while (lo < hi) {
            int mid = (lo + hi) >> 1;
            if (adj_row[mid] < r) lo = mid + 1; else hi = mid;
        }
        g_rowptr[r] = lo;
    }
}

// ---------------------------------------------------------------------------
// Tensor-core GEMM (mma.sync bf16, 3-term split), term-major MMA ordering.
// CTA 128x128, BK=32, 4 warps (2x2), warp tile 64x64, cp.async double buffer.
// ---------------------------------------------------------------------------
#define BM 128
#define BN 128
#define BK 32
#define KSTRIDE 40                 // bf16 per smem row (32 + 8 pad)
#define ASPLIT  (128 * KSTRIDE)    // 5120 bf16 per split-tile
#define ABUF    (2 * ASPLIT)       // hi+lo
#define B_BASE  (2 * ABUF)         // B region starts after A double buffer
#define SMEM_BF16_TOTAL (4 * ABUF) // 40960 bf16 = 81920 bytes

__device__ __forceinline__ void cp_async16(uint32_t dst, const void* src, bool pred)
{
    int sz = pred ? 16 : 0;
    asm volatile("cp.async.cg.shared.global [%0], [%1], 16, %2;\n"
                 :: "r"(dst), "l"(src), "r"(sz));
}
__device__ __forceinline__ void cp_commit() { asm volatile("cp.async.commit_group;\n"); }
__device__ __forceinline__ void cp_wait0()  { asm volatile("cp.async.wait_group 0;\n"); }

__device__ __forceinline__ void mma_bf16(float c[4], const uint32_t a[4],
                                         const uint32_t b[2])
{
    asm volatile(
        "mma.sync.aligned.m16n8k16.row.col.f32.bf16.bf16.f32 "
        "{%0,%1,%2,%3}, {%4,%5,%6,%7}, {%8,%9}, {%0,%1,%2,%3};\n"
        : "+f"(c[0]), "+f"(c[1]), "+f"(c[2]), "+f"(c[3])
        : "r"(a[0]), "r"(a[1]), "r"(a[2]), "r"(a[3]), "r"(b[0]), "r"(b[1]));
}

__global__ __launch_bounds__(128) void gemm_tc_kernel()
{
    extern __shared__ __nv_bfloat16 smem[];
    const int tid  = threadIdx.x;
    const int lane = tid & 31;
    const int wid  = tid >> 5;            // 0..3
    const int wm   = (wid & 1) * 64;
    const int wn   = (wid >> 1) * 64;
    const int m0   = blockIdx.y * BM;
    const int n0   = blockIdx.x * BN;
    const int grp  = lane >> 2;           // 0..7
    const int tig  = lane & 3;            // 0..3

    const uint32_t smem_u32 = (uint32_t)__cvta_generic_to_shared(smem);

    float acc[4][8][4];
#pragma unroll
    for (int mi = 0; mi < 4; mi++)
#pragma unroll
        for (int ni = 0; ni < 8; ni++)
#pragma unroll
            for (int q = 0; q < 4; q++) acc[mi][ni][q] = 0.f;

    // --- tile loader: thread t loads row t (4 chunks x 2 splits, A and B) ---
    const int row  = tid;                 // 0..127
    const int gmA  = m0 + row;
    const bool pA  = (gmA < M_NODES);
    const int gnB  = n0 + row;            // always < 512

    auto load_tile = [&](int buf, int k0) {
#pragma unroll
        for (int c = 0; c < 4; c++) {
            uint32_t dA = smem_u32 + (uint32_t)((buf * ABUF + row * KSTRIDE + c * 8) * 2);
            cp_async16(dA,            &g_xhi[(size_t)gmA * K_IN + k0 + c * 8], pA);
            cp_async16(dA + ASPLIT*2, &g_xlo[(size_t)gmA * K_IN + k0 + c * 8], pA);
            uint32_t dB = smem_u32 + (uint32_t)((B_BASE + buf * ABUF + row * KSTRIDE + c * 8) * 2);
            cp_async16(dB,            &g_whi[(size_t)gnB * K_IN + k0 + c * 8], true);
            cp_async16(dB + ASPLIT*2, &g_wlo[(size_t)gnB * K_IN + k0 + c * 8], true);
        }
        cp_commit();
    };

    load_tile(0, 0);

    const int NT = K_IN / BK;             // 16
    for (int t = 0; t < NT; t++) {
        cp_wait0();
        __syncthreads();
        if (t + 1 < NT) load_tile((t + 1) & 1, (t + 1) * BK);

        const int buf = t & 1;
        const __nv_bfloat16* sA = smem + buf * ABUF;
        const __nv_bfloat16* sB = smem + B_BASE + buf * ABUF;

#pragma unroll
        for (int ks = 0; ks < 2; ks++) {
            const int col = ks * 16 + tig * 2;
            uint32_t ahi[4][4], alo[4][4];
#pragma unroll
            for (int mi = 0; mi < 4; mi++) {
                int r0 = wm + mi * 16 + grp;
                const __nv_bfloat16* ph = sA + r0 * KSTRIDE;
                ahi[mi][0] = *(const uint32_t*)(ph + col);
                ahi[mi][1] = *(const uint32_t*)(ph + 8 * KSTRIDE + col);
                ahi[mi][2] = *(const uint32_t*)(ph + col + 8);
                ahi[mi][3] = *(const uint32_t*)(ph + 8 * KSTRIDE + col + 8);
                const __nv_bfloat16* pl = ph + ASPLIT;
                alo[mi][0] = *(const uint32_t*)(pl + col);
                alo[mi][1] = *(const uint32_t*)(pl + 8 * KSTRIDE + col);
                alo[mi][2] = *(const uint32_t*)(pl + col + 8);
                alo[mi][3] = *(const uint32_t*)(pl + 8 * KSTRIDE + col + 8);
            }
#pragma unroll
            for (int nh = 0; nh < 2; nh++) {
                uint32_t bhi[4][2], blo[4][2];
#pragma unroll
                for (int nj = 0; nj < 4; nj++) {
                    int rn = wn + (nh * 4 + nj) * 8 + grp;
                    const __nv_bfloat16* ph = sB + rn * KSTRIDE;
                    bhi[nj][0] = *(const uint32_t*)(ph + col);
                    bhi[nj][1] = *(const uint32_t*)(ph + col + 8);
                    const __nv_bfloat16* pl = ph + ASPLIT;
                    blo[nj][0] = *(const uint32_t*)(pl + col);
                    blo[nj][1] = *(const uint32_t*)(pl + col + 8);
                }
                // --- term-major: 16 independent MMAs per term ---
#pragma unroll
                for (int mi = 0; mi < 4; mi++)
#pragma unroll
                    for (int nj = 0; nj < 4; nj++)
                        mma_bf16(acc[mi][nh * 4 + nj], ahi[mi], bhi[nj]);
#pragma unroll
                for (int mi = 0; mi < 4; mi++)
#pragma unroll
                    for (int nj = 0; nj < 4; nj++)
                        mma_bf16(acc[mi][nh * 4 + nj], ahi[mi], blo[nj]);
#pragma unroll
                for (int mi = 0; mi < 4; mi++)
#pragma unroll
                    for (int nj = 0; nj < 4; nj++)
                        mma_bf16(acc[mi][nh * 4 + nj], alo[mi], bhi[nj]);
            }
        }
        __syncthreads();
    }

    // --- epilogue: acc -> g_xfts ---
#pragma unroll
    for (int mi = 0; mi < 4; mi++) {
        int gm = m0 + wm + mi * 16 + grp;
#pragma unroll
        for (int ni = 0; ni < 8; ni++) {
            int gn = n0 + wn + ni * 8 + tig * 2;
            if (gm < M_NODES)
                *(float2*)&g_xfts[(size_t)gm * N_HID + gn] =
                    make_float2(acc[mi][ni][0], acc[mi][ni][1]);
            if (gm + 8 < M_NODES)
                *(float2*)&g_xfts[(size_t)(gm + 8) * N_HID + gn] =
                    make_float2(acc[mi][ni][2], acc[mi][ni][3]);
        }
    }
}

// ---------------------------------------------------------------------------
// SPMM + bias + PReLU (rowptr precomputed, 2-deep MLP)
// ---------------------------------------------------------------------------
__global__ __launch_bounds__(128) void spmm_bias_prelu_kernel(
    const float* __restrict__ adj_vals,
    const int* __restrict__ adj_col,
    const float* __restrict__ bias,
    const float* __restrict__ prelu_a,
    float* __restrict__ out)
{
    const int r = blockIdx.x;
    const int c = threadIdx.x * 4;
    const int start = g_rowptr[r];
    const int end   = g_rowptr[r + 1];

    float4 acc0 = make_float4(0.f, 0.f, 0.f, 0.f);
    float4 acc1 = make_float4(0.f, 0.f, 0.f, 0.f);

    int e = start;
    for (; e + 1 < end; e += 2) {
        const float v0 = __ldg(&adj_vals[e]);
        const int   c0 = __ldg(&adj_col[e]);
        const float v1 = __ldg(&adj_vals[e + 1]);
        const int   c1 = __ldg(&adj_col[e + 1]);
        const float4 f0 = *reinterpret_cast<const float4*>(&g_xfts[(size_t)c0 * N_HID + c]);
        const float4 f1 = *reinterpret_cast<const float4*>(&g_xfts[(size_t)c1 * N_HID + c]);
        acc0.x += v0 * f0.x; acc0.y += v0 * f0.y; acc0.z += v0 * f0.z; acc0.w += v0 * f0.w;
        acc1.x += v1 * f1.x; acc1.y += v1 * f1.y; acc1.z += v1 * f1.z; acc1.w += v1 * f1.w;
    }
    if (e < end) {
        const float v0 = __ldg(&adj_vals[e]);
        const int   c0 = __ldg(&adj_col[e]);
        const float4 f0 = *reinterpret_cast<const float4*>(&g_xfts[(size_t)c0 * N_HID + c]);
        acc0.x += v0 * f0.x; acc0.y += v0 * f0.y; acc0.z += v0 * f0.z; acc0.w += v0 * f0.w;
    }

    const float4 b4 = *reinterpret_cast<const float4*>(&bias[c]);
    const float a = *prelu_a;
    float4 o;
    o.x = acc0.x + acc1.x + b4.x;
    o.y = acc0.y + acc1.y + b4.y;
    o.z = acc0.z + acc1.z + b4.z;
    o.w = acc0.w + acc1.w + b4.w;
    o.x = (o.x >= 0.f) ? o.x : a * o.x;
    o.y = (o.y >= 0.f) ? o.y : a * o.y;
    o.z = (o.z >= 0.f) ? o.z : a * o.z;
    o.w = (o.w >= 0.f) ? o.w : a * o.w;
    *reinterpret_cast<float4*>(&out[(size_t)r * N_HID + c]) = o;
}

extern "C" void kernel_launch(void* const* d_in, const int* in_sizes, int n_in,
                              void* d_out, int out_size)
{
    const float* x        = (const float*)d_in[0];
    const float* fc_w     = (const float*)d_in[1];
    const float* bias     = (const float*)d_in[2];
    const float* prelu_a  = (const float*)d_in[3];
    const float* adj_vals = (const float*)d_in[4];
    const int*   adj_row  = (const int*)d_in[5];
    const int*   adj_col  = (const int*)d_in[6];
    float*       out      = (float*)d_out;

    cudaFuncSetAttribute(gemm_tc_kernel,
                         cudaFuncAttributeMaxDynamicSharedMemorySize,
                         SMEM_BF16_TOTAL * 2);

    prep_kernel<<<XBLK + WBLK + RBLK, 256>>>(x, fc_w, adj_row);

    dim3 ggrid(N_HID / BN, (M_NODES + BM - 1) / BM);   // 4 x 79
    gemm_tc_kernel<<<ggrid, 128, SMEM_BF16_TOTAL * 2>>>();

    spmm_bias_prelu_kernel<<<M_NODES, 128>>>(adj_vals, adj_col, bias, prelu_a, out);
}

// round 6
// speedup vs baseline: 1.9788x; 1.1488x over previous
#include <cuda_runtime.h>
#include <cuda_bf16.h>
#include <cstdint>

#define M_NODES 10000
#define K_IN    512
#define N_HID   512
#define N_EDGES 160000

// Scratch (no allocations allowed)
__device__ float         g_xfts[M_NODES * N_HID];
__device__ __nv_bfloat16 g_xhi[M_NODES * K_IN];
__device__ __nv_bfloat16 g_xlo[M_NODES * K_IN];
__device__ __nv_bfloat16 g_whi[N_HID * K_IN];
__device__ __nv_bfloat16 g_wlo[N_HID * K_IN];
__device__ int           g_rowptr[M_NODES + 1];

// ---------------------------------------------------------------------------
// Fused prep: split X, split W (fp32 -> bf16 hi+lo), build rowptr.
// ---------------------------------------------------------------------------
#define XBLK 5000
#define WBLK 256
#define RBLK 40

__global__ __launch_bounds__(256) void prep_kernel(
    const float* __restrict__ x,
    const float* __restrict__ fc_w,
    const int* __restrict__ adj_row)
{
    const int b = blockIdx.x;
    if (b < XBLK) {
        int i = b * 256 + threadIdx.x;
        if (i * 4 >= M_NODES * K_IN) return;
        float4 v = reinterpret_cast<const float4*>(x)[i];
        __nv_bfloat16 hx = __float2bfloat16_rn(v.x);
        __nv_bfloat16 hy = __float2bfloat16_rn(v.y);
        __nv_bfloat16 hz = __float2bfloat16_rn(v.z);
        __nv_bfloat16 hw = __float2bfloat16_rn(v.w);
        __nv_bfloat16 lx = __float2bfloat16_rn(v.x - __bfloat162float(hx));
        __nv_bfloat16 ly = __float2bfloat16_rn(v.y - __bfloat162float(hy));
        __nv_bfloat16 lz = __float2bfloat16_rn(v.z - __bfloat162float(hz));
        __nv_bfloat16 lw = __float2bfloat16_rn(v.w - __bfloat162float(hw));
        reinterpret_cast<__nv_bfloat162*>(g_xhi)[2 * i]     = __nv_bfloat162(hx, hy);
        reinterpret_cast<__nv_bfloat162*>(g_xhi)[2 * i + 1] = __nv_bfloat162(hz, hw);
        reinterpret_cast<__nv_bfloat162*>(g_xlo)[2 * i]     = __nv_bfloat162(lx, ly);
        reinterpret_cast<__nv_bfloat162*>(g_xlo)[2 * i + 1] = __nv_bfloat162(lz, lw);
    } else if (b < XBLK + WBLK) {
        int i = (b - XBLK) * 256 + threadIdx.x;
        if (i * 4 >= N_HID * K_IN) return;
        float4 v = reinterpret_cast<const float4*>(fc_w)[i];
        __nv_bfloat16 hx = __float2bfloat16_rn(v.x);
        __nv_bfloat16 hy = __float2bfloat16_rn(v.y);
        __nv_bfloat16 hz = __float2bfloat16_rn(v.z);
        __nv_bfloat16 hw = __float2bfloat16_rn(v.w);
        __nv_bfloat16 lx = __float2bfloat16_rn(v.x - __bfloat162float(hx));
        __nv_bfloat16 ly = __float2bfloat16_rn(v.y - __bfloat162float(hy));
        __nv_bfloat16 lz = __float2bfloat16_rn(v.z - __bfloat162float(hz));
        __nv_bfloat16 lw = __float2bfloat16_rn(v.w - __bfloat162float(hw));
        reinterpret_cast<__nv_bfloat162*>(g_whi)[2 * i]     = __nv_bfloat162(hx, hy);
        reinterpret_cast<__nv_bfloat162*>(g_whi)[2 * i + 1] = __nv_bfloat162(hz, hw);
        reinterpret_cast<__nv_bfloat162*>(g_wlo)[2 * i]     = __nv_bfloat162(lx, ly);
        reinterpret_cast<__nv_bfloat162*>(g_wlo)[2 * i + 1] = __nv_bfloat162(lz, lw);
    } else {
        int r = (b - XBLK - WBLK) * 256 + threadIdx.x;
        if (r > M_NODES) return;
        int lo = 0, hi = N_EDGES;
        while (lo < hi) {
            int mid = (lo + hi) >> 1;
            if (adj_row[mid] < r) lo = mid + 1; else hi = mid;
        }
        g_rowptr[r] = lo;
    }
}

// ---------------------------------------------------------------------------
// Tensor-core GEMM (mma.sync bf16, 3-term split).
// CTA 128x128, BK=32, 256 threads = 8 warps (2m x 4n), warp tile 64x32.
// cp.async double buffer, term-major MMA ordering.
// ---------------------------------------------------------------------------
#define BM 128
#define BN 128
#define BK 32
#define KSTRIDE 40                 // bf16 per smem row (32 + 8 pad)
#define ASPLIT  (128 * KSTRIDE)    // 5120 bf16 per split-tile
#define ABUF    (2 * ASPLIT)       // hi+lo
#define B_BASE  (2 * ABUF)
#define SMEM_BF16_TOTAL (4 * ABUF) // 80 KB per stage

__device__ __forceinline__ void cp_async16(uint32_t dst, const void* src, bool pred)
{
    int sz = pred ? 16 : 0;
    asm volatile("cp.async.cg.shared.global [%0], [%1], 16, %2;\n"
                 :: "r"(dst), "l"(src), "r"(sz));
}
__device__ __forceinline__ void cp_commit() { asm volatile("cp.async.commit_group;\n"); }
__device__ __forceinline__ void cp_wait0()  { asm volatile("cp.async.wait_group 0;\n"); }

__device__ __forceinline__ void mma_bf16(float c[4], const uint32_t a[4],
                                         const uint32_t b[2])
{
    asm volatile(
        "mma.sync.aligned.m16n8k16.row.col.f32.bf16.bf16.f32 "
        "{%0,%1,%2,%3}, {%4,%5,%6,%7}, {%8,%9}, {%0,%1,%2,%3};\n"
        : "+f"(c[0]), "+f"(c[1]), "+f"(c[2]), "+f"(c[3])
        : "r"(a[0]), "r"(a[1]), "r"(a[2]), "r"(a[3]), "r"(b[0]), "r"(b[1]));
}

__global__ __launch_bounds__(256) void gemm_tc_kernel()
{
    extern __shared__ __nv_bfloat16 smem[];
    const int tid  = threadIdx.x;
    const int lane = tid & 31;
    const int wid  = tid >> 5;            // 0..7
    const int wm   = (wid & 1) * 64;      // 2 warps over M
    const int wn   = (wid >> 1) * 32;     // 4 warps over N
    const int m0   = blockIdx.y * BM;
    const int n0   = blockIdx.x * BN;
    const int grp  = lane >> 2;           // 0..7
    const int tig  = lane & 3;            // 0..3

    const uint32_t smem_u32 = (uint32_t)__cvta_generic_to_shared(smem);

    float acc[4][4][4];
#pragma unroll
    for (int mi = 0; mi < 4; mi++)
#pragma unroll
        for (int ni = 0; ni < 4; ni++)
#pragma unroll
            for (int q = 0; q < 4; q++) acc[mi][ni][q] = 0.f;

    // --- tile loader: 256 threads, thread -> (row = tid>>1, 2x16B chunks) ---
    const int row  = tid >> 1;            // 0..127
    const int half = tid & 1;             // 0..1
    const int gmA  = m0 + row;
    const bool pA  = (gmA < M_NODES);
    const int gnB  = n0 + row;            // always < 512

    auto load_tile = [&](int buf, int k0) {
#pragma unroll
        for (int c = 0; c < 2; c++) {
            int ch = half * 2 + c;        // 0..3 (16B chunks of the 64B row)
            uint32_t dA = smem_u32 + (uint32_t)((buf * ABUF + row * KSTRIDE + ch * 8) * 2);
            cp_async16(dA,            &g_xhi[(size_t)gmA * K_IN + k0 + ch * 8], pA);
            cp_async16(dA + ASPLIT*2, &g_xlo[(size_t)gmA * K_IN + k0 + ch * 8], pA);
            uint32_t dB = smem_u32 + (uint32_t)((B_BASE + buf * ABUF + row * KSTRIDE + ch * 8) * 2);
            cp_async16(dB,            &g_whi[(size_t)gnB * K_IN + k0 + ch * 8], true);
            cp_async16(dB + ASPLIT*2, &g_wlo[(size_t)gnB * K_IN + k0 + ch * 8], true);
        }
        cp_commit();
    };

    load_tile(0, 0);

    const int NT = K_IN / BK;             // 16
    for (int t = 0; t < NT; t++) {
        cp_wait0();
        __syncthreads();
        if (t + 1 < NT) load_tile((t + 1) & 1, (t + 1) * BK);

        const int buf = t & 1;
        const __nv_bfloat16* sA = smem + buf * ABUF;
        const __nv_bfloat16* sB = smem + B_BASE + buf * ABUF;

#pragma unroll
        for (int ks = 0; ks < 2; ks++) {
            const int col = ks * 16 + tig * 2;
            uint32_t ahi[4][4], alo[4][4];
#pragma unroll
            for (int mi = 0; mi < 4; mi++) {
                int r0 = wm + mi * 16 + grp;
                const __nv_bfloat16* ph = sA + r0 * KSTRIDE;
                ahi[mi][0] = *(const uint32_t*)(ph + col);
                ahi[mi][1] = *(const uint32_t*)(ph + 8 * KSTRIDE + col);
                ahi[mi][2] = *(const uint32_t*)(ph + col + 8);
                ahi[mi][3] = *(const uint32_t*)(ph + 8 * KSTRIDE + col + 8);
                const __nv_bfloat16* pl = ph + ASPLIT;
                alo[mi][0] = *(const uint32_t*)(pl + col);
                alo[mi][1] = *(const uint32_t*)(pl + 8 * KSTRIDE + col);
                alo[mi][2] = *(const uint32_t*)(pl + col + 8);
                alo[mi][3] = *(const uint32_t*)(pl + 8 * KSTRIDE + col + 8);
            }
            uint32_t bhi[4][2], blo[4][2];
#pragma unroll
            for (int nj = 0; nj < 4; nj++) {
                int rn = wn + nj * 8 + grp;
                const __nv_bfloat16* ph = sB + rn * KSTRIDE;
                bhi[nj][0] = *(const uint32_t*)(ph + col);
                bhi[nj][1] = *(const uint32_t*)(ph + col + 8);
                const __nv_bfloat16* pl = ph + ASPLIT;
                blo[nj][0] = *(const uint32_t*)(pl + col);
                blo[nj][1] = *(const uint32_t*)(pl + col + 8);
            }
            // --- term-major: 16 independent MMAs per term ---
#pragma unroll
            for (int mi = 0; mi < 4; mi++)
#pragma unroll
                for (int nj = 0; nj < 4; nj++)
                    mma_bf16(acc[mi][nj], ahi[mi], bhi[nj]);
#pragma unroll
            for (int mi = 0; mi < 4; mi++)
#pragma unroll
                for (int nj = 0; nj < 4; nj++)
                    mma_bf16(acc[mi][nj], ahi[mi], blo[nj]);
#pragma unroll
            for (int mi = 0; mi < 4; mi++)
#pragma unroll
                for (int nj = 0; nj < 4; nj++)
                    mma_bf16(acc[mi][nj], alo[mi], bhi[nj]);
        }
        __syncthreads();
    }

    // --- epilogue: acc -> g_xfts ---
#pragma unroll
    for (int mi = 0; mi < 4; mi++) {
        int gm = m0 + wm + mi * 16 + grp;
#pragma unroll
        for (int nj = 0; nj < 4; nj++) {
            int gn = n0 + wn + nj * 8 + tig * 2;
            if (gm < M_NODES)
                *(float2*)&g_xfts[(size_t)gm * N_HID + gn] =
                    make_float2(acc[mi][nj][0], acc[mi][nj][1]);
            if (gm + 8 < M_NODES)
                *(float2*)&g_xfts[(size_t)(gm + 8) * N_HID + gn] =
                    make_float2(acc[mi][nj][2], acc[mi][nj][3]);
        }
    }
}

// ---------------------------------------------------------------------------
// SPMM + bias + PReLU (rowptr precomputed, 2-deep MLP)
// ---------------------------------------------------------------------------
__global__ __launch_bounds__(128) void spmm_bias_prelu_kernel(
    const float* __restrict__ adj_vals,
    const int* __restrict__ adj_col,
    const float* __restrict__ bias,
    const float* __restrict__ prelu_a,
    float* __restrict__ out)
{
    const int r = blockIdx.x;
    const int c = threadIdx.x * 4;
    const int start = g_rowptr[r];
    const int end   = g_rowptr[r + 1];

    float4 acc0 = make_float4(0.f, 0.f, 0.f, 0.f);
    float4 acc1 = make_float4(0.f, 0.f, 0.f, 0.f);

    int e = start;
    for (; e + 1 < end; e += 2) {
        const float v0 = __ldg(&adj_vals[e]);
        const int   c0 = __ldg(&adj_col[e]);
        const float v1 = __ldg(&adj_vals[e + 1]);
        const int   c1 = __ldg(&adj_col[e + 1]);
        const float4 f0 = *reinterpret_cast<const float4*>(&g_xfts[(size_t)c0 * N_HID + c]);
        const float4 f1 = *reinterpret_cast<const float4*>(&g_xfts[(size_t)c1 * N_HID + c]);
        acc0.x += v0 * f0.x; acc0.y += v0 * f0.y; acc0.z += v0 * f0.z; acc0.w += v0 * f0.w;
        acc1.x += v1 * f1.x; acc1.y += v1 * f1.y; acc1.z += v1 * f1.z; acc1.w += v1 * f1.w;
    }
    if (e < end) {
        const float v0 = __ldg(&adj_vals[e]);
        const int   c0 = __ldg(&adj_col[e]);
        const float4 f0 = *reinterpret_cast<const float4*>(&g_xfts[(size_t)c0 * N_HID + c]);
        acc0.x += v0 * f0.x; acc0.y += v0 * f0.y; acc0.z += v0 * f0.z; acc0.w += v0 * f0.w;
    }

    const float4 b4 = *reinterpret_cast<const float4*>(&bias[c]);
    const float a = *prelu_a;
    float4 o;
    o.x = acc0.x + acc1.x + b4.x;
    o.y = acc0.y + acc1.y + b4.y;
    o.z = acc0.z + acc1.z + b4.z;
    o.w = acc0.w + acc1.w + b4.w;
    o.x = (o.x >= 0.f) ? o.x : a * o.x;
    o.y = (o.y >= 0.f) ? o.y : a * o.y;
    o.z = (o.z >= 0.f) ? o.z : a * o.z;
    o.w = (o.w >= 0.f) ? o.w : a * o.w;
    *reinterpret_cast<float4*>(&out[(size_t)r * N_HID + c]) = o;
}

extern "C" void kernel_launch(void* const* d_in, const int* in_sizes, int n_in,
                              void* d_out, int out_size)
{
    const float* x        = (const float*)d_in[0];
    const float* fc_w     = (const float*)d_in[1];
    const float* bias     = (const float*)d_in[2];
    const float* prelu_a  = (const float*)d_in[3];
    const float* adj_vals = (const float*)d_in[4];
    const int*   adj_row  = (const int*)d_in[5];
    const int*   adj_col  = (const int*)d_in[6];
    float*       out      = (float*)d_out;

    cudaFuncSetAttribute(gemm_tc_kernel,
                         cudaFuncAttributeMaxDynamicSharedMemorySize,
                         SMEM_BF16_TOTAL * 2);

    prep_kernel<<<XBLK + WBLK + RBLK, 256>>>(x, fc_w, adj_row);

    dim3 ggrid(N_HID / BN, (M_NODES + BM - 1) / BM);   // 4 x 79
    gemm_tc_kernel<<<ggrid, 256, SMEM_BF16_TOTAL * 2>>>();

    spmm_bias_prelu_kernel<<<M_NODES, 128>>>(adj_vals, adj_col, bias, prelu_a, out);
}

// round 7
// speedup vs baseline: 2.1357x; 1.0793x over previous
#include <cuda_runtime.h>
#include <cuda_bf16.h>
#include <cstdint>

#define M_NODES 10000
#define K_IN    512
#define N_HID   512
#define N_EDGES 160000

// Scratch (no allocations allowed)
__device__ float         g_xfts[M_NODES * N_HID];
__device__ __nv_bfloat16 g_xhi[M_NODES * K_IN];
__device__ __nv_bfloat16 g_xlo[M_NODES * K_IN];
__device__ __nv_bfloat16 g_whi[N_HID * K_IN];
__device__ __nv_bfloat16 g_wlo[N_HID * K_IN];
__device__ int           g_rowptr[M_NODES + 1];

// ---------------------------------------------------------------------------
// Fused prep: split X (2 float4/thread), split W, build rowptr.
// ---------------------------------------------------------------------------
#define XBLK 2500
#define WBLK 256
#define RBLK 40

__device__ __forceinline__ void split4(float4 v, __nv_bfloat16* hi_arr,
                                       __nv_bfloat16* lo_arr, int i)
{
    __nv_bfloat16 hx = __float2bfloat16_rn(v.x);
    __nv_bfloat16 hy = __float2bfloat16_rn(v.y);
    __nv_bfloat16 hz = __float2bfloat16_rn(v.z);
    __nv_bfloat16 hw = __float2bfloat16_rn(v.w);
    __nv_bfloat16 lx = __float2bfloat16_rn(v.x - __bfloat162float(hx));
    __nv_bfloat16 ly = __float2bfloat16_rn(v.y - __bfloat162float(hy));
    __nv_bfloat16 lz = __float2bfloat16_rn(v.z - __bfloat162float(hz));
    __nv_bfloat16 lw = __float2bfloat16_rn(v.w - __bfloat162float(hw));
    reinterpret_cast<__nv_bfloat162*>(hi_arr)[2 * i]     = __nv_bfloat162(hx, hy);
    reinterpret_cast<__nv_bfloat162*>(hi_arr)[2 * i + 1] = __nv_bfloat162(hz, hw);
    reinterpret_cast<__nv_bfloat162*>(lo_arr)[2 * i]     = __nv_bfloat162(lx, ly);
    reinterpret_cast<__nv_bfloat162*>(lo_arr)[2 * i + 1] = __nv_bfloat162(lz, lw);
}

__global__ __launch_bounds__(256) void prep_kernel(
    const float* __restrict__ x,
    const float* __restrict__ fc_w,
    const int* __restrict__ adj_row)
{
    const int b = blockIdx.x;
    if (b < XBLK) {
        int i0 = b * 512 + threadIdx.x;
        float4 v0 = reinterpret_cast<const float4*>(x)[i0];
        float4 v1 = reinterpret_cast<const float4*>(x)[i0 + 256];
        split4(v0, g_xhi, g_xlo, i0);
        split4(v1, g_xhi, g_xlo, i0 + 256);
    } else if (b < XBLK + WBLK) {
        int i = (b - XBLK) * 256 + threadIdx.x;
        float4 v = reinterpret_cast<const float4*>(fc_w)[i];
        split4(v, g_whi, g_wlo, i);
    } else {
        int r = (b - XBLK - WBLK) * 256 + threadIdx.x;
        if (r > M_NODES) return;
        int lo = 0, hi = N_EDGES;
        while (lo < hi) {
            int mid = (lo + hi) >> 1;
            if (adj_row[mid] < r) lo = mid + 1; else hi = mid;
        }
        g_rowptr[r] = lo;
    }
}

// ---------------------------------------------------------------------------
// Tensor-core GEMM (mma.sync bf16, 3-term split), ldmatrix fragment loads.
// CTA 128x64, BK=32, 256 threads = 8 warps (4m x 2n), warp tile 32x32.
// cp.async double buffer; 30KB/stage -> 2 CTAs/SM.
// ---------------------------------------------------------------------------
#define BM 128
#define BN 64
#define BK 32
#define KSTRIDE 40                        // bf16 per smem row (32 + 8 pad)
#define A_LO_OFF 5120                     // 128*40
#define B_OFF    10240
#define B_LO_REL 2560                     // 64*40
#define STAGE    15360                    // elements per stage
#define SMEM_BYTES (2 * STAGE * 2)        // 61440

__device__ __forceinline__ void cp_async16(uint32_t dst, const void* src, bool pred)
{
    int sz = pred ? 16 : 0;
    asm volatile("cp.async.cg.shared.global [%0], [%1], 16, %2;\n"
                 :: "r"(dst), "l"(src), "r"(sz));
}
__device__ __forceinline__ void cp_commit() { asm volatile("cp.async.commit_group;\n"); }
__device__ __forceinline__ void cp_wait0()  { asm volatile("cp.async.wait_group 0;\n"); }

#define LDSM_X4(r0, r1, r2, r3, addr) \
    asm volatile("ldmatrix.sync.aligned.m8n8.x4.shared.b16 {%0,%1,%2,%3}, [%4];" \
                 : "=r"(r0), "=r"(r1), "=r"(r2), "=r"(r3) : "r"(addr))

__device__ __forceinline__ void mma_bf16(float c[4], const uint32_t a[4],
                                         const uint32_t b[2])
{
    asm volatile(
        "mma.sync.aligned.m16n8k16.row.col.f32.bf16.bf16.f32 "
        "{%0,%1,%2,%3}, {%4,%5,%6,%7}, {%8,%9}, {%0,%1,%2,%3};\n"
        : "+f"(c[0]), "+f"(c[1]), "+f"(c[2]), "+f"(c[3])
        : "r"(a[0]), "r"(a[1]), "r"(a[2]), "r"(a[3]), "r"(b[0]), "r"(b[1]));
}

__global__ __launch_bounds__(256, 2) void gemm_tc_kernel()
{
    extern __shared__ __nv_bfloat16 smem[];
    const int tid  = threadIdx.x;
    const int lane = tid & 31;
    const int wid  = tid >> 5;            // 0..7
    const int wm   = (wid & 3) * 32;      // 4 warps over M
    const int wn   = (wid >> 2) * 32;     // 2 warps over N
    const int m0   = blockIdx.y * BM;
    const int n0   = blockIdx.x * BN;
    const int grp  = lane >> 2;           // 0..7
    const int tig  = lane & 3;            // 0..3

    const uint32_t smem_u32 = (uint32_t)__cvta_generic_to_shared(smem);

    float acc[2][4][4];
#pragma unroll
    for (int mi = 0; mi < 2; mi++)
#pragma unroll
        for (int ni = 0; ni < 4; ni++)
#pragma unroll
            for (int q = 0; q < 4; q++) acc[mi][ni][q] = 0.f;

    // --- loaders ---
    const int rowA  = tid >> 1;           // 0..127
    const int halfA = tid & 1;
    const int gmA   = m0 + rowA;
    const bool pA   = (gmA < M_NODES);
    const int rowB  = tid >> 2;           // 0..63
    const int chB   = tid & 3;            // 0..3
    const int gnB   = n0 + rowB;          // < 512 always

    auto load_tile = [&](int buf, int k0) {
        uint32_t sbase = smem_u32 + (uint32_t)(buf * STAGE) * 2;
#pragma unroll
        for (int c = 0; c < 2; c++) {
            int ch = halfA * 2 + c;       // 0..3
            uint32_t dA = sbase + (uint32_t)(rowA * KSTRIDE + ch * 8) * 2;
            cp_async16(dA,                &g_xhi[(size_t)gmA * K_IN + k0 + ch * 8], pA);
            cp_async16(dA + A_LO_OFF * 2, &g_xlo[(size_t)gmA * K_IN + k0 + ch * 8], pA);
        }
        uint32_t dB = sbase + (uint32_t)(B_OFF + rowB * KSTRIDE + chB * 8) * 2;
        cp_async16(dB,                &g_whi[(size_t)gnB * K_IN + k0 + chB * 8], true);
        cp_async16(dB + B_LO_REL * 2, &g_wlo[(size_t)gnB * K_IN + k0 + chB * 8], true);
        cp_commit();
    };

    load_tile(0, 0);

    // ldmatrix per-lane address components
    const int a_row = wm + ((lane >> 3) & 1) * 8 + (lane & 7);  // within warp A tile
    const int a_seg = (lane >> 4) * 8;                          // k segment select
    const int b_row = wn + (lane >> 4) * 8 + (lane & 7);        // within nj pair
    const int b_seg = ((lane >> 3) & 1) * 8;

    const int NT = K_IN / BK;             // 16
    for (int t = 0; t < NT; t++) {
        cp_wait0();
        __syncthreads();
        if (t + 1 < NT) load_tile((t + 1) & 1, (t + 1) * BK);

        const uint32_t sbase = smem_u32 + (uint32_t)((t & 1) * STAGE) * 2;

#pragma unroll
        for (int ks = 0; ks < 2; ks++) {
            const int kcol = ks * 16;
            uint32_t ahi[2][4], alo[2][4];
#pragma unroll
            for (int mi = 0; mi < 2; mi++) {
                uint32_t addr = sbase + (uint32_t)((a_row + mi * 16) * KSTRIDE + a_seg + kcol) * 2;
                LDSM_X4(ahi[mi][0], ahi[mi][1], ahi[mi][2], ahi[mi][3], addr);
                LDSM_X4(alo[mi][0], alo[mi][1], alo[mi][2], alo[mi][3], addr + A_LO_OFF * 2);
            }
            uint32_t bhi[4][2], blo[4][2];
#pragma unroll
            for (int njp = 0; njp < 2; njp++) {
                uint32_t addr = sbase + (uint32_t)(B_OFF + (b_row + njp * 16) * KSTRIDE + b_seg + kcol) * 2;
                LDSM_X4(bhi[njp * 2][0], bhi[njp * 2][1],
                        bhi[njp * 2 + 1][0], bhi[njp * 2 + 1][1], addr);
                LDSM_X4(blo[njp * 2][0], blo[njp * 2][1],
                        blo[njp * 2 + 1][0], blo[njp * 2 + 1][1], addr + B_LO_REL * 2);
            }
            // term-major: 8 independent MMAs per term
#pragma unroll
            for (int mi = 0; mi < 2; mi++)
#pragma unroll
                for (int nj = 0; nj < 4; nj++)
                    mma_bf16(acc[mi][nj], ahi[mi], bhi[nj]);
#pragma unroll
            for (int mi = 0; mi < 2; mi++)
#pragma unroll
                for (int nj = 0; nj < 4; nj++)
                    mma_bf16(acc[mi][nj], ahi[mi], blo[nj]);
#pragma unroll
            for (int mi = 0; mi < 2; mi++)
#pragma unroll
                for (int nj = 0; nj < 4; nj++)
                    mma_bf16(acc[mi][nj], alo[mi], bhi[nj]);
        }
        __syncthreads();
    }

    // --- epilogue ---
#pragma unroll
    for (int mi = 0; mi < 2; mi++) {
        int gm = m0 + wm + mi * 16 + grp;
#pragma unroll
        for (int nj = 0; nj < 4; nj++) {
            int gn = n0 + wn + nj * 8 + tig * 2;
            if (gm < M_NODES)
                *(float2*)&g_xfts[(size_t)gm * N_HID + gn] =
                    make_float2(acc[mi][nj][0], acc[mi][nj][1]);
            if (gm + 8 < M_NODES)
                *(float2*)&g_xfts[(size_t)(gm + 8) * N_HID + gn] =
                    make_float2(acc[mi][nj][2], acc[mi][nj][3]);
        }
    }
}

// ---------------------------------------------------------------------------
// SPMM + bias + PReLU (rowptr precomputed, 4-deep MLP)
// ---------------------------------------------------------------------------
__global__ __launch_bounds__(128) void spmm_bias_prelu_kernel(
    const float* __restrict__ adj_vals,
    const int* __restrict__ adj_col,
    const float* __restrict__ bias,
    const float* __restrict__ prelu_a,
    float* __restrict__ out)
{
    const int r = blockIdx.x;
    const int c = threadIdx.x * 4;
    const int start = g_rowptr[r];
    const int end   = g_rowptr[r + 1];

    float4 a0 = make_float4(0.f, 0.f, 0.f, 0.f);
    float4 a1 = make_float4(0.f, 0.f, 0.f, 0.f);
    float4 a2 = make_float4(0.f, 0.f, 0.f, 0.f);
    float4 a3 = make_float4(0.f, 0.f, 0.f, 0.f);

    int e = start;
    for (; e + 3 < end; e += 4) {
        const float v0 = __ldg(&adj_vals[e]);
        const float v1 = __ldg(&adj_vals[e + 1]);
        const float v2 = __ldg(&adj_vals[e + 2]);
        const float v3 = __ldg(&adj_vals[e + 3]);
        const int   c0 = __ldg(&adj_col[e]);
        const int   c1 = __ldg(&adj_col[e + 1]);
        const int   c2 = __ldg(&adj_col[e + 2]);
        const int   c3 = __ldg(&adj_col[e + 3]);
        const float4 f0 = *reinterpret_cast<const float4*>(&g_xfts[(size_t)c0 * N_HID + c]);
        const float4 f1 = *reinterpret_cast<const float4*>(&g_xfts[(size_t)c1 * N_HID + c]);
        const float4 f2 = *reinterpret_cast<const float4*>(&g_xfts[(size_t)c2 * N_HID + c]);
        const float4 f3 = *reinterpret_cast<const float4*>(&g_xfts[(size_t)c3 * N_HID + c]);
        a0.x += v0 * f0.x; a0.y += v0 * f0.y; a0.z += v0 * f0.z; a0.w += v0 * f0.w;
        a1.x += v1 * f1.x; a1.y += v1 * f1.y; a1.z += v1 * f1.z; a1.w += v1 * f1.w;
        a2.x += v2 * f2.x; a2.y += v2 * f2.y; a2.z += v2 * f2.z; a2.w += v2 * f2.w;
        a3.x += v3 * f3.x; a3.y += v3 * f3.y; a3.z += v3 * f3.z; a3.w += v3 * f3.w;
    }
    for (; e < end; e++) {
        const float v0 = __ldg(&adj_vals[e]);
        const int   c0 = __ldg(&adj_col[e]);
        const float4 f0 = *reinterpret_cast<const float4*>(&g_xfts[(size_t)c0 * N_HID + c]);
        a0.x += v0 * f0.x; a0.y += v0 * f0.y; a0.z += v0 * f0.z; a0.w += v0 * f0.w;
    }

    const float4 b4 = *reinterpret_cast<const float4*>(&bias[c]);
    const float a = *prelu_a;
    float4 o;
    o.x = (a0.x + a1.x) + (a2.x + a3.x) + b4.x;
    o.y = (a0.y + a1.y) + (a2.y + a3.y) + b4.y;
    o.z = (a0.z + a1.z) + (a2.z + a3.z) + b4.z;
    o.w = (a0.w + a1.w) + (a2.w + a3.w) + b4.w;
    o.x = (o.x >= 0.f) ? o.x : a * o.x;
    o.y = (o.y >= 0.f) ? o.y : a * o.y;
    o.z = (o.z >= 0.f) ? o.z : a * o.z;
    o.w = (o.w >= 0.f) ? o.w : a * o.w;
    *reinterpret_cast<float4*>(&out[(size_t)r * N_HID + c]) = o;
}

extern "C" void kernel_launch(void* const* d_in, const int* in_sizes, int n_in,
                              void* d_out, int out_size)
{
    const float* x        = (const float*)d_in[0];
    const float* fc_w     = (const float*)d_in[1];
    const float* bias     = (const float*)d_in[2];
    const float* prelu_a  = (const float*)d_in[3];
    const float* adj_vals = (const float*)d_in[4];
    const int*   adj_row  = (const int*)d_in[5];
    const int*   adj_col  = (const int*)d_in[6];
    float*       out      = (float*)d_out;

    cudaFuncSetAttribute(gemm_tc_kernel,
                         cudaFuncAttributeMaxDynamicSharedMemorySize, SMEM_BYTES);

    prep_kernel<<<XBLK + WBLK + RBLK, 256>>>(x, fc_w, adj_row);

    dim3 ggrid(N_HID / BN, (M_NODES + BM - 1) / BM);   // 8 x 79
    gemm_tc_kernel<<<ggrid, 256, SMEM_BYTES>>>();

    spmm_bias_prelu_kernel<<<M_NODES, 128>>>(adj_vals, adj_col, bias, prelu_a, out);
}